// round 9
// baseline (speedup 1.0000x reference)
#include <cuda_runtime.h>
#include <cuda_bf16.h>
#include <cstdint>

#define BSZ   8
#define NT    128
#define CH    1024
#define KH    4
#define HDIM  512
#define GDIM  2048
#define NHEAD 8
#define CPH   16
#define NCTA  128

// ---- smem layout for k_lstm (bytes) ----
#define WLO_BYTES   131072                 // 8 warps * 32 kc * 32 lanes * 16B
#define HT_STRIDE32 260                    // u32 row stride: banks 4*b+t4 conflict-free in mma reads
#define HTHI_OFF    131072
#define HTLO_OFF    (HTHI_OFF + 8320)      // 8 rows * 260 u32 * 4B
#define PG_OFF      (HTLO_OFF + 8320)
#define PG_LD       9
#define LSTM_SMEM   (PG_OFF + 128 * PG_LD * 4)   // 152320 B

// ---------------- static device scratch ----------------
__device__ float g_xT[KH * NT * BSZ * CH];                 // [k][t][b][c]
__device__ float g_xproj[NHEAD * NT * BSZ * GDIM];         // [hd][t][b][g]
__device__ unsigned g_hhi[2 * NHEAD * BSZ * 256];          // packed bf16 hi pairs [par][hd][b][c/2]
__device__ unsigned g_hlo[2 * NHEAD * BSZ * 256];          // packed bf16 lo pairs
__device__ uint4 g_whi[NHEAD * 16 * 8192];                 // frag-order bf16 hi
__device__ uint4 g_wlo[NHEAD * 16 * 8192];                 // frag-order bf16 lo
__device__ unsigned g_flag[NHEAD * CPH];

// ---------------- helpers ----------------
__device__ __forceinline__ uint32_t f2tf(float f) {
    uint32_t u; asm("cvt.rna.tf32.f32 %0, %1;" : "=r"(u) : "f"(f)); return u;
}
__device__ __forceinline__ void mma_tf32(float* d, const uint32_t* a, const uint32_t* b) {
    asm volatile("mma.sync.aligned.m16n8k8.row.col.f32.tf32.tf32.f32 "
        "{%0,%1,%2,%3}, {%4,%5,%6,%7}, {%8,%9}, {%0,%1,%2,%3};"
        : "+f"(d[0]), "+f"(d[1]), "+f"(d[2]), "+f"(d[3])
        : "r"(a[0]), "r"(a[1]), "r"(a[2]), "r"(a[3]), "r"(b[0]), "r"(b[1]));
}
__device__ __forceinline__ void mma_bf(float* d, uint4 a, unsigned b0, unsigned b1) {
    asm volatile("mma.sync.aligned.m16n8k16.row.col.f32.bf16.bf16.f32 "
        "{%0,%1,%2,%3},{%4,%5,%6,%7},{%8,%9},{%0,%1,%2,%3};"
        : "+f"(d[0]), "+f"(d[1]), "+f"(d[2]), "+f"(d[3])
        : "r"(a.x), "r"(a.y), "r"(a.z), "r"(a.w), "r"(b0), "r"(b1));
}
// split two floats into packed bf16 hi (returned) and lo (out param); low 16 bits = first arg
__device__ __forceinline__ unsigned bfsplit2(float x, float y, unsigned &lo) {
    __nv_bfloat16 hx = __float2bfloat16_rn(x), hy = __float2bfloat16_rn(y);
    float rx = x - __bfloat162float(hx), ry = y - __bfloat162float(hy);
    __nv_bfloat16 lx = __float2bfloat16_rn(rx), ly = __float2bfloat16_rn(ry);
    unsigned short uhx = *(unsigned short*)&hx, uhy = *(unsigned short*)&hy;
    unsigned short ulx = *(unsigned short*)&lx, uly = *(unsigned short*)&ly;
    lo = (unsigned)ulx | ((unsigned)uly << 16);
    return (unsigned)uhx | ((unsigned)uhy << 16);
}

// ---------------- init ----------------
__global__ void k_init() {
    int idx = blockIdx.x * blockDim.x + threadIdx.x;
    if (idx < NHEAD * CPH) g_flag[idx] = 0u;
    if (idx < 2 * NHEAD * BSZ * 256) { g_hhi[idx] = 0u; g_hlo[idx] = 0u; }
}

// ---------------- transpose x: [b][t][c][k] -> [k][t][b][c] ----------------
__global__ void k_xT(const float* __restrict__ x) {
    int c = blockIdx.x * 128 + threadIdx.x;
    int t = blockIdx.y, b = blockIdx.z;
    float4 v = *(const float4*)&x[(size_t)((b * NT + t) * CH + c) * KH];
    const size_t plane = (size_t)NT * BSZ * CH;
    const size_t o = (size_t)(t * BSZ + b) * CH + c;
    g_xT[o]             = v.x;
    g_xT[o + plane]     = v.y;
    g_xT[o + 2 * plane] = v.z;
    g_xT[o + 3 * plane] = v.w;
}

// ---------------- Whh -> bf16 hi/lo fragments in mma A-frag order ----------------
__global__ void k_wfrag(const float* __restrict__ Wf, const float* __restrict__ Wb) {
    int fi = blockIdx.x * 256 + threadIdx.x;
    int lane = fi & 31, kc = (fi >> 5) & 31, w = (fi >> 10) & 7;
    int ci = (fi >> 13) & 15, hd = fi >> 17;
    int dir = hd >> 2, kk = hd & 3;
    const float* W = (dir ? Wb : Wf) + (size_t)kk * GDIM * HDIM;
    int gID = lane >> 2, t2 = (lane & 3) * 2;
    int r0 = w * 16 + gID, r1 = r0 + 8;
    int gA = (r0 >> 5) * HDIM + ci * 32 + (r0 & 31);
    int gB = (r1 >> 5) * HDIM + ci * 32 + (r1 & 31);
    int c0 = kc * 16 + t2;
    float2 e0 = *(const float2*)&W[(size_t)gA * HDIM + c0];
    float2 e1 = *(const float2*)&W[(size_t)gB * HDIM + c0];
    float2 e2 = *(const float2*)&W[(size_t)gA * HDIM + c0 + 8];
    float2 e3 = *(const float2*)&W[(size_t)gB * HDIM + c0 + 8];
    uint4 hi, lo;
    hi.x = bfsplit2(e0.x, e0.y, lo.x);
    hi.y = bfsplit2(e1.x, e1.y, lo.y);
    hi.z = bfsplit2(e2.x, e2.y, lo.z);
    hi.w = bfsplit2(e3.x, e3.y, lo.w);
    g_whi[fi] = hi;
    g_wlo[fi] = lo;
}

// ---------------- phase-1 GEMM via tf32 mma.sync (unchanged) ----------------
#define ALD 36

__global__ __launch_bounds__(256) void k_gemm(
    const float* __restrict__ Wih_f, const float* __restrict__ Wih_b,
    const float* __restrict__ bih_f, const float* __restrict__ bhh_f,
    const float* __restrict__ bih_b, const float* __restrict__ bhh_b)
{
    __shared__ uint32_t As[128 * ALD];
    __shared__ uint32_t Bs[128 * ALD];

    const int hd = blockIdx.z, dir = hd >> 2, k = hd & 3;
    const float* A = g_xT + (size_t)k * (NT * BSZ * CH) + (size_t)blockIdx.y * 128 * CH;
    const float* W = (dir ? Wih_b : Wih_f) + (size_t)k * GDIM * CH + (size_t)blockIdx.x * 128 * CH;
    const float* bi = (dir ? bih_b : bih_f) + k * GDIM;
    const float* bh = (dir ? bhh_b : bhh_f) + k * GDIM;

    const int tid = threadIdx.x, lane = tid & 31, wid = tid >> 5;
    const int wm = (wid & 1) * 64, wn = (wid >> 1) * 32;
    const int grp = lane >> 2, tig = lane & 3;

    float acc[4][4][4];
    #pragma unroll
    for (int a = 0; a < 4; a++)
        #pragma unroll
        for (int b = 0; b < 4; b++)
            #pragma unroll
            for (int c = 0; c < 4; c++) acc[a][b][c] = 0.f;

    const int lr = tid >> 3;
    const int lcf = (tid & 7) * 4;
    const int kb = lcf >> 3, lo = (lcf >> 2) & 1;
    const int sbase = kb * 8 + lo;

    float4 pa[4], pb[4];
    #pragma unroll
    for (int i = 0; i < 4; i++) {
        pa[i] = *(const float4*)&A[(size_t)(lr + 32 * i) * CH + lcf];
        pb[i] = *(const float4*)&W[(size_t)(lr + 32 * i) * CH + lcf];
    }

    for (int c0 = 0; c0 < CH; c0 += 32) {
        if (c0) __syncthreads();
        #pragma unroll
        for (int i = 0; i < 4; i++) {
            int r = lr + 32 * i;
            As[r * ALD + sbase + 0] = f2tf(pa[i].x);
            As[r * ALD + sbase + 2] = f2tf(pa[i].y);
            As[r * ALD + sbase + 4] = f2tf(pa[i].z);
            As[r * ALD + sbase + 6] = f2tf(pa[i].w);
            Bs[r * ALD + sbase + 0] = f2tf(pb[i].x);
            Bs[r * ALD + sbase + 2] = f2tf(pb[i].y);
            Bs[r * ALD + sbase + 4] = f2tf(pb[i].z);
            Bs[r * ALD + sbase + 6] = f2tf(pb[i].w);
        }
        __syncthreads();
        if (c0 + 32 < CH) {
            #pragma unroll
            for (int i = 0; i < 4; i++) {
                pa[i] = *(const float4*)&A[(size_t)(lr + 32 * i) * CH + c0 + 32 + lcf];
                pb[i] = *(const float4*)&W[(size_t)(lr + 32 * i) * CH + c0 + 32 + lcf];
            }
        }
        #pragma unroll
        for (int kk = 0; kk < 4; kk++) {
            uint32_t af[4][4], bf[4][2];
            #pragma unroll
            for (int mt = 0; mt < 4; mt++) {
                int r = wm + mt * 16 + grp;
                uint2 v0 = *(const uint2*)&As[r * ALD + kk * 8 + 2 * tig];
                uint2 v1 = *(const uint2*)&As[(r + 8) * ALD + kk * 8 + 2 * tig];
                af[mt][0] = v0.x; af[mt][1] = v1.x; af[mt][2] = v0.y; af[mt][3] = v1.y;
            }
            #pragma unroll
            for (int nt = 0; nt < 4; nt++) {
                int r = wn + nt * 8 + grp;
                uint2 v = *(const uint2*)&Bs[r * ALD + kk * 8 + 2 * tig];
                bf[nt][0] = v.x; bf[nt][1] = v.y;
            }
            #pragma unroll
            for (int mt = 0; mt < 4; mt++)
                #pragma unroll
                for (int nt = 0; nt < 4; nt++)
                    mma_tf32(acc[mt][nt], af[mt], bf[nt]);
        }
    }

    const int gm0 = blockIdx.y * 128 + wm;
    const int gn0 = blockIdx.x * 128 + wn;
    #pragma unroll
    for (int nt = 0; nt < 4; nt++) {
        int g = gn0 + nt * 8 + 2 * tig;
        float b0 = bi[g] + bh[g];
        float b1 = bi[g + 1] + bh[g + 1];
        #pragma unroll
        for (int mt = 0; mt < 4; mt++) {
            int m = gm0 + mt * 16 + grp;
            {
                int t = m >> 3, b = m & 7;
                float2 s; s.x = acc[mt][nt][0] + b0; s.y = acc[mt][nt][1] + b1;
                *(float2*)&g_xproj[(((size_t)hd * NT + t) * BSZ + b) * GDIM + g] = s;
            }
            {
                int m2 = m + 8;
                int t = m2 >> 3, b = m2 & 7;
                float2 s; s.x = acc[mt][nt][2] + b0; s.y = acc[mt][nt][3] + b1;
                *(float2*)&g_xproj[(((size_t)hd * NT + t) * BSZ + b) * GDIM + g] = s;
            }
        }
    }
}

// ---------------- phase-2: persistent recurrent scan (bf16x3 tensor cores) ----------------
// h exchanged PRE-SPLIT as packed bf16 hi/lo u32 pairs — consumer copy is a raw 8KB memcpy.
__global__ __launch_bounds__(256) void k_lstm(float* __restrict__ out) {
    extern __shared__ char smem[];
    uint4*    wlo_s  = (uint4*)smem;
    unsigned* hthi32 = (unsigned*)(smem + HTHI_OFF);
    unsigned* htlo32 = (unsigned*)(smem + HTLO_OFF);
    float*    pg     = (float*)(smem + PG_OFF);

    const int cta = blockIdx.x;
    const int hd  = cta >> 4;
    const int ci  = cta & 15;
    const int h0  = ci * 32;
    const int dir = hd >> 2;
    const int k   = hd & 3;
    const int tid = threadIdx.x;
    const int wid = tid >> 5, lane = tid & 31;
    const int gID = lane >> 2, t4 = lane & 3;

    // finalize role: tid<128 -> (b, h-pair)
    const int fb = tid & 7, fhp = tid >> 3;

    // preload W_lo fragments into smem (128 KB, once)
    const uint4* wlo_cta = g_wlo + (size_t)(hd * 16 + ci) * 8192;
    #pragma unroll 4
    for (int i = tid; i < 8192; i += 256) wlo_s[i] = __ldg(&wlo_cta[i]);

    // preload W_hi fragments into registers (128 regs/thread)
    uint4 ahi[32];
    const uint4* whi_cta = g_whi + (size_t)(hd * 16 + ci) * 8192 + wid * 1024 + lane;
    #pragma unroll
    for (int kc = 0; kc < 32; kc++) ahi[kc] = __ldg(&whi_cta[kc * 32]);

    float c_state0 = 0.f, c_state1 = 0.f;
    volatile unsigned* flg = g_flag + hd * CPH;

    // prefetch xproj for step 0 (pairs: g = gate*512 + h0 + 2*fhp)
    int t = dir ? (NT - 1) : 0;
    float2 xp[4];
    if (tid < 128) {
        const float* xb = &g_xproj[(((size_t)hd * NT + t) * BSZ + fb) * GDIM + h0 + 2 * fhp];
        #pragma unroll
        for (int g = 0; g < 4; g++) xp[g] = *(const float2*)(xb + g * HDIM);
    }

    for (int s = 0; s < NT; s++) {
        const int par = s & 1;
        t = dir ? (NT - 1 - s) : s;

        // ---- copy packed h hi/lo (8 KB) from L2 into padded smem ----
        {
            const uint4* shi = (const uint4*)(g_hhi + (size_t)(par * NHEAD + hd) * (BSZ * 256));
            const uint4* slo = (const uint4*)(g_hlo + (size_t)(par * NHEAD + hd) * (BSZ * 256));
            #pragma unroll
            for (int j = 0; j < 2; j++) {
                int idx = tid + j * 256;                 // 512 uint4 per array
                int row = idx >> 6, col = (idx & 63) * 4;
                *(uint4*)(hthi32 + row * HT_STRIDE32 + col) = __ldcg(&shi[idx]);
                *(uint4*)(htlo32 + row * HT_STRIDE32 + col) = __ldcg(&slo[idx]);
            }
        }
        __syncthreads();

        // ---- mma: warp owns 16 gate rows x full k=512 ----
        float acc_a[4] = {0.f, 0.f, 0.f, 0.f};
        float acc_b[4] = {0.f, 0.f, 0.f, 0.f};
        {
            const unsigned* bh = hthi32 + gID * HT_STRIDE32;
            const unsigned* bl = htlo32 + gID * HT_STRIDE32;
            const uint4* wl = wlo_s + wid * 1024 + lane;
            #pragma unroll
            for (int kc = 0; kc < 32; kc++) {
                unsigned bh0 = bh[kc * 8 + t4];
                unsigned bh1 = bh[kc * 8 + t4 + 4];
                unsigned bl0 = bl[kc * 8 + t4];
                unsigned bl1 = bl[kc * 8 + t4 + 4];
                uint4 alo = wl[kc * 32];
                mma_bf(acc_a, ahi[kc], bh0, bh1);   // Whi * h_hi
                mma_bf(acc_b, ahi[kc], bl0, bl1);   // Whi * h_lo
                mma_bf(acc_a, alo,     bh0, bh1);   // Wlo * h_hi
            }
        }
        {
            int r = wid * 16 + gID;
            int t2 = t4 * 2;
            pg[r * PG_LD + t2]           = acc_a[0] + acc_b[0];
            pg[r * PG_LD + t2 + 1]       = acc_a[1] + acc_b[1];
            pg[(r + 8) * PG_LD + t2]     = acc_a[2] + acc_b[2];
            pg[(r + 8) * PG_LD + t2 + 1] = acc_a[3] + acc_b[3];
        }
        __syncthreads();

        // ---- finalize: tid<128, thread = (b, h-pair); produces 2 h values ----
        if (tid < 128) {
            float hn[2];
            #pragma unroll
            for (int e = 0; e < 2; e++) {
                const int hh = 2 * fhp + e;
                float pre0 = pg[(0 * 32 + hh) * PG_LD + fb] + (e ? xp[0].y : xp[0].x);
                float pre1 = pg[(1 * 32 + hh) * PG_LD + fb] + (e ? xp[1].y : xp[1].x);
                float pre2 = pg[(2 * 32 + hh) * PG_LD + fb] + (e ? xp[2].y : xp[2].x);
                float pre3 = pg[(3 * 32 + hh) * PG_LD + fb] + (e ? xp[3].y : xp[3].x);
                float ig = 1.f / (1.f + expf(-pre0));
                float fg = 1.f / (1.f + expf(-pre1));
                float gt = tanhf(pre2);
                float og = 1.f / (1.f + expf(-pre3));
                float &cs = e ? c_state1 : c_state0;
                cs = fg * cs + ig * gt;
                hn[e] = og * tanhf(cs);
                out[(((size_t)fb * NT + t) * (2 * HDIM) + dir * HDIM + h0 + hh) * KH + k] = hn[e];
            }
            // pack pre-split h for next step's consumers
            unsigned lo;
            unsigned hi = bfsplit2(hn[0], hn[1], lo);
            size_t off = (size_t)((par ^ 1) * NHEAD + hd) * (BSZ * 256) + fb * 256 + (h0 >> 1) + fhp;
            g_hhi[off] = hi;
            g_hlo[off] = lo;
        }

        if (s < NT - 1) {
            // prefetch xproj for next step (overlaps barrier)
            int tn = dir ? (NT - 2 - s) : (s + 1);
            if (tid < 128) {
                const float* xb = &g_xproj[(((size_t)hd * NT + tn) * BSZ + fb) * GDIM + h0 + 2 * fhp];
                #pragma unroll
                for (int g = 0; g < 4; g++) xp[g] = *(const float2*)(xb + g * HDIM);
            }
            if (tid < 128) __threadfence();
            __syncthreads();
            if (tid == 0)
                *(volatile unsigned*)&g_flag[hd * CPH + ci] = (unsigned)(s + 1);
            if (tid < CPH) {
                while (flg[tid] <= (unsigned)s) { }
            }
            __syncthreads();
        }
    }
}

// ---------------- launch ----------------
extern "C" void kernel_launch(void* const* d_in, const int* in_sizes, int n_in,
                              void* d_out, int out_size) {
    const float* x     = (const float*)d_in[0];
    const float* Wih_f = (const float*)d_in[1];
    const float* Whh_f = (const float*)d_in[2];
    const float* bih_f = (const float*)d_in[3];
    const float* bhh_f = (const float*)d_in[4];
    const float* Wih_b = (const float*)d_in[5];
    const float* Whh_b = (const float*)d_in[6];
    const float* bih_b = (const float*)d_in[7];
    const float* bhh_b = (const float*)d_in[8];
    float* out = (float*)d_out;

    static int smem_set = 0;
    if (!smem_set) {
        cudaFuncSetAttribute(k_lstm, cudaFuncAttributeMaxDynamicSharedMemorySize, LSTM_SMEM);
        smem_set = 1;
    }

    k_init<<<256, 256>>>();
    dim3 gx(CH / 128, NT, BSZ);
    k_xT<<<gx, 128>>>(x);
    k_wfrag<<<4096, 256>>>(Whh_f, Whh_b);
    dim3 gg(GDIM / 128, (NT * BSZ) / 128, NHEAD);
    k_gemm<<<gg, 256>>>(Wih_f, Wih_b, bih_f, bhh_f, bih_b, bhh_b);
    k_lstm<<<NCTA, 256, LSTM_SMEM>>>(out);
}

// round 10
// speedup vs baseline: 1.4795x; 1.4795x over previous
#include <cuda_runtime.h>
#include <cuda_bf16.h>
#include <cstdint>

#define BSZ   8
#define NT    128
#define CH    1024
#define KH    4
#define HDIM  512
#define GDIM  2048
#define NHEAD 8
#define CPH   16
#define NCTA  128

// ---- smem layout for k_lstm (bytes) ----
#define HT_STRIDE32 260
#define HTHI_OFF    131072
#define HTLO_OFF    (HTHI_OFF + 8320)
#define PG_OFF      (HTLO_OFF + 8320)
#define PG_LD       9
#define LSTM_SMEM   (PG_OFF + 128 * PG_LD * 4)   // 152320 B

// ---------------- static device scratch ----------------
__device__ float g_xT[KH * NT * BSZ * CH];                 // [k][t][b][c]
__device__ float g_xproj[NHEAD * NT * BSZ * GDIM];         // [hd][t][b][g]
__device__ unsigned g_hhi[2 * NHEAD * BSZ * 256];          // packed bf16 hi pairs [par][hd][b][c/2]
__device__ unsigned g_hlo[2 * NHEAD * BSZ * 256];          // packed bf16 lo pairs
__device__ uint4 g_whi[NHEAD * 16 * 8192];                 // frag-order bf16 hi
__device__ uint4 g_wlo[NHEAD * 16 * 8192];                 // frag-order bf16 lo
__device__ unsigned g_flag[NHEAD * CPH];

// ---------------- helpers ----------------
__device__ __forceinline__ uint32_t f2tf(float f) {
    uint32_t u; asm("cvt.rna.tf32.f32 %0, %1;" : "=r"(u) : "f"(f)); return u;
}
__device__ __forceinline__ void mma_tf32(float* d, const uint32_t* a, const uint32_t* b) {
    asm volatile("mma.sync.aligned.m16n8k8.row.col.f32.tf32.tf32.f32 "
        "{%0,%1,%2,%3}, {%4,%5,%6,%7}, {%8,%9}, {%0,%1,%2,%3};"
        : "+f"(d[0]), "+f"(d[1]), "+f"(d[2]), "+f"(d[3])
        : "r"(a[0]), "r"(a[1]), "r"(a[2]), "r"(a[3]), "r"(b[0]), "r"(b[1]));
}
__device__ __forceinline__ void mma_bf(float* d, uint4 a, unsigned b0, unsigned b1) {
    asm volatile("mma.sync.aligned.m16n8k16.row.col.f32.bf16.bf16.f32 "
        "{%0,%1,%2,%3},{%4,%5,%6,%7},{%8,%9},{%0,%1,%2,%3};"
        : "+f"(d[0]), "+f"(d[1]), "+f"(d[2]), "+f"(d[3])
        : "r"(a.x), "r"(a.y), "r"(a.z), "r"(a.w), "r"(b0), "r"(b1));
}
// split two floats into packed bf16 hi (returned) and lo (out param); low 16 bits = first arg
__device__ __forceinline__ unsigned bfsplit2(float x, float y, unsigned &lo) {
    __nv_bfloat16 hx = __float2bfloat16_rn(x), hy = __float2bfloat16_rn(y);
    float rx = x - __bfloat162float(hx), ry = y - __bfloat162float(hy);
    __nv_bfloat16 lx = __float2bfloat16_rn(rx), ly = __float2bfloat16_rn(ry);
    unsigned short uhx = *(unsigned short*)&hx, uhy = *(unsigned short*)&hy;
    unsigned short ulx = *(unsigned short*)&lx, uly = *(unsigned short*)&ly;
    lo = (unsigned)ulx | ((unsigned)uly << 16);
    return (unsigned)uhx | ((unsigned)uhy << 16);
}
__device__ __forceinline__ float fsigmoid(float x) {
    return 1.f / (1.f + __expf(-x));
}
__device__ __forceinline__ float ftanh(float x) {
    float e = __expf(-2.f * x);
    return (1.f - e) / (1.f + e);
}

// ---------------- init ----------------
__global__ void k_init() {
    int idx = blockIdx.x * blockDim.x + threadIdx.x;
    if (idx < NHEAD * CPH) g_flag[idx] = 0u;
    if (idx < 2 * NHEAD * BSZ * 256) { g_hhi[idx] = 0u; g_hlo[idx] = 0u; }
}

// ---------------- transpose x: [b][t][c][k] -> [k][t][b][c] ----------------
__global__ void k_xT(const float* __restrict__ x) {
    int c = blockIdx.x * 128 + threadIdx.x;
    int t = blockIdx.y, b = blockIdx.z;
    float4 v = *(const float4*)&x[(size_t)((b * NT + t) * CH + c) * KH];
    const size_t plane = (size_t)NT * BSZ * CH;
    const size_t o = (size_t)(t * BSZ + b) * CH + c;
    g_xT[o]             = v.x;
    g_xT[o + plane]     = v.y;
    g_xT[o + 2 * plane] = v.z;
    g_xT[o + 3 * plane] = v.w;
}

// ---------------- Whh -> bf16 hi/lo fragments in mma A-frag order ----------------
__global__ void k_wfrag(const float* __restrict__ Wf, const float* __restrict__ Wb) {
    int fi = blockIdx.x * 256 + threadIdx.x;
    int lane = fi & 31, kc = (fi >> 5) & 31, w = (fi >> 10) & 7;
    int ci = (fi >> 13) & 15, hd = fi >> 17;
    int dir = hd >> 2, kk = hd & 3;
    const float* W = (dir ? Wb : Wf) + (size_t)kk * GDIM * HDIM;
    int gID = lane >> 2, t2 = (lane & 3) * 2;
    int r0 = w * 16 + gID, r1 = r0 + 8;
    int gA = (r0 >> 5) * HDIM + ci * 32 + (r0 & 31);
    int gB = (r1 >> 5) * HDIM + ci * 32 + (r1 & 31);
    int c0 = kc * 16 + t2;
    float2 e0 = *(const float2*)&W[(size_t)gA * HDIM + c0];
    float2 e1 = *(const float2*)&W[(size_t)gB * HDIM + c0];
    float2 e2 = *(const float2*)&W[(size_t)gA * HDIM + c0 + 8];
    float2 e3 = *(const float2*)&W[(size_t)gB * HDIM + c0 + 8];
    uint4 hi, lo;
    hi.x = bfsplit2(e0.x, e0.y, lo.x);
    hi.y = bfsplit2(e1.x, e1.y, lo.y);
    hi.z = bfsplit2(e2.x, e2.y, lo.z);
    hi.w = bfsplit2(e3.x, e3.y, lo.w);
    g_whi[fi] = hi;
    g_wlo[fi] = lo;
}

// ---------------- phase-1 GEMM via tf32 mma.sync ----------------
#define ALD 36

__global__ __launch_bounds__(256) void k_gemm(
    const float* __restrict__ Wih_f, const float* __restrict__ Wih_b,
    const float* __restrict__ bih_f, const float* __restrict__ bhh_f,
    const float* __restrict__ bih_b, const float* __restrict__ bhh_b)
{
    __shared__ uint32_t As[128 * ALD];
    __shared__ uint32_t Bs[128 * ALD];

    const int hd = blockIdx.z, dir = hd >> 2, k = hd & 3;
    const float* A = g_xT + (size_t)k * (NT * BSZ * CH) + (size_t)blockIdx.y * 128 * CH;
    const float* W = (dir ? Wih_b : Wih_f) + (size_t)k * GDIM * CH + (size_t)blockIdx.x * 128 * CH;
    const float* bi = (dir ? bih_b : bih_f) + k * GDIM;
    const float* bh = (dir ? bhh_b : bhh_f) + k * GDIM;

    const int tid = threadIdx.x, lane = tid & 31, wid = tid >> 5;
    const int wm = (wid & 1) * 64, wn = (wid >> 1) * 32;
    const int grp = lane >> 2, tig = lane & 3;

    float acc[4][4][4];
    #pragma unroll
    for (int a = 0; a < 4; a++)
        #pragma unroll
        for (int b = 0; b < 4; b++)
            #pragma unroll
            for (int c = 0; c < 4; c++) acc[a][b][c] = 0.f;

    const int lr = tid >> 3;
    const int lcf = (tid & 7) * 4;
    const int kb = lcf >> 3, lo = (lcf >> 2) & 1;
    const int sbase = kb * 8 + lo;

    float4 pa[4], pb[4];
    #pragma unroll
    for (int i = 0; i < 4; i++) {
        pa[i] = *(const float4*)&A[(size_t)(lr + 32 * i) * CH + lcf];
        pb[i] = *(const float4*)&W[(size_t)(lr + 32 * i) * CH + lcf];
    }

    for (int c0 = 0; c0 < CH; c0 += 32) {
        if (c0) __syncthreads();
        #pragma unroll
        for (int i = 0; i < 4; i++) {
            int r = lr + 32 * i;
            As[r * ALD + sbase + 0] = f2tf(pa[i].x);
            As[r * ALD + sbase + 2] = f2tf(pa[i].y);
            As[r * ALD + sbase + 4] = f2tf(pa[i].z);
            As[r * ALD + sbase + 6] = f2tf(pa[i].w);
            Bs[r * ALD + sbase + 0] = f2tf(pb[i].x);
            Bs[r * ALD + sbase + 2] = f2tf(pb[i].y);
            Bs[r * ALD + sbase + 4] = f2tf(pb[i].z);
            Bs[r * ALD + sbase + 6] = f2tf(pb[i].w);
        }
        __syncthreads();
        if (c0 + 32 < CH) {
            #pragma unroll
            for (int i = 0; i < 4; i++) {
                pa[i] = *(const float4*)&A[(size_t)(lr + 32 * i) * CH + c0 + 32 + lcf];
                pb[i] = *(const float4*)&W[(size_t)(lr + 32 * i) * CH + c0 + 32 + lcf];
            }
        }
        #pragma unroll
        for (int kk = 0; kk < 4; kk++) {
            uint32_t af[4][4], bf[4][2];
            #pragma unroll
            for (int mt = 0; mt < 4; mt++) {
                int r = wm + mt * 16 + grp;
                uint2 v0 = *(const uint2*)&As[r * ALD + kk * 8 + 2 * tig];
                uint2 v1 = *(const uint2*)&As[(r + 8) * ALD + kk * 8 + 2 * tig];
                af[mt][0] = v0.x; af[mt][1] = v1.x; af[mt][2] = v0.y; af[mt][3] = v1.y;
            }
            #pragma unroll
            for (int nt = 0; nt < 4; nt++) {
                int r = wn + nt * 8 + grp;
                uint2 v = *(const uint2*)&Bs[r * ALD + kk * 8 + 2 * tig];
                bf[nt][0] = v.x; bf[nt][1] = v.y;
            }
            #pragma unroll
            for (int mt = 0; mt < 4; mt++)
                #pragma unroll
                for (int nt = 0; nt < 4; nt++)
                    mma_tf32(acc[mt][nt], af[mt], bf[nt]);
        }
    }

    const int gm0 = blockIdx.y * 128 + wm;
    const int gn0 = blockIdx.x * 128 + wn;
    #pragma unroll
    for (int nt = 0; nt < 4; nt++) {
        int g = gn0 + nt * 8 + 2 * tig;
        float b0 = bi[g] + bh[g];
        float b1 = bi[g + 1] + bh[g + 1];
        #pragma unroll
        for (int mt = 0; mt < 4; mt++) {
            int m = gm0 + mt * 16 + grp;
            {
                int t = m >> 3, b = m & 7;
                float2 s; s.x = acc[mt][nt][0] + b0; s.y = acc[mt][nt][1] + b1;
                *(float2*)&g_xproj[(((size_t)hd * NT + t) * BSZ + b) * GDIM + g] = s;
            }
            {
                int m2 = m + 8;
                int t = m2 >> 3, b = m2 & 7;
                float2 s; s.x = acc[mt][nt][2] + b0; s.y = acc[mt][nt][3] + b1;
                *(float2*)&g_xproj[(((size_t)hd * NT + t) * BSZ + b) * GDIM + g] = s;
            }
        }
    }
}

// ---------------- phase-2: persistent recurrent scan (bf16x3 tensor cores) ----------------
// Pre-split h exchange (8 KB/step), 256-thread finalize with shfl pair-pack,
// single-thread release fence.
__global__ __launch_bounds__(256) void k_lstm(float* __restrict__ out) {
    extern __shared__ char smem[];
    uint4*    wlo_s  = (uint4*)smem;
    unsigned* hthi32 = (unsigned*)(smem + HTHI_OFF);
    unsigned* htlo32 = (unsigned*)(smem + HTLO_OFF);
    float*    pg     = (float*)(smem + PG_OFF);

    const int cta = blockIdx.x;
    const int hd  = cta >> 4;
    const int ci  = cta & 15;
    const int h0  = ci * 32;
    const int dir = hd >> 2;
    const int k   = hd & 3;
    const int tid = threadIdx.x;
    const int wid = tid >> 5, lane = tid & 31;
    const int gID = lane >> 2, t4 = lane & 3;

    // finalize role: warp = batch, lane = h index within the CTA's 32
    const int fb = wid, fhh = lane;

    // preload W_lo fragments into smem (128 KB, once)
    const uint4* wlo_cta = g_wlo + (size_t)(hd * 16 + ci) * 8192;
    #pragma unroll 4
    for (int i = tid; i < 8192; i += 256) wlo_s[i] = __ldg(&wlo_cta[i]);

    // preload W_hi fragments into registers (128 regs/thread)
    uint4 ahi[32];
    const uint4* whi_cta = g_whi + (size_t)(hd * 16 + ci) * 8192 + wid * 1024 + lane;
    #pragma unroll
    for (int kc = 0; kc < 32; kc++) ahi[kc] = __ldg(&whi_cta[kc * 32]);

    float c_state = 0.f;
    volatile unsigned* flg = g_flag + hd * CPH;

    // prefetch xproj for step 0
    int t = dir ? (NT - 1) : 0;
    float xp[4];
    {
        const float* xb = &g_xproj[(((size_t)hd * NT + t) * BSZ + fb) * GDIM + h0 + fhh];
        #pragma unroll
        for (int g = 0; g < 4; g++) xp[g] = __ldg(xb + g * HDIM);
    }

    for (int s = 0; s < NT; s++) {
        const int par = s & 1;
        t = dir ? (NT - 1 - s) : s;

        // ---- copy packed h hi/lo (8 KB) from L2 into padded smem ----
        {
            const uint4* shi = (const uint4*)(g_hhi + (size_t)(par * NHEAD + hd) * (BSZ * 256));
            const uint4* slo = (const uint4*)(g_hlo + (size_t)(par * NHEAD + hd) * (BSZ * 256));
            #pragma unroll
            for (int j = 0; j < 2; j++) {
                int idx = tid + j * 256;                 // 512 uint4 per array
                int row = idx >> 6, col = (idx & 63) * 4;
                *(uint4*)(hthi32 + row * HT_STRIDE32 + col) = __ldcg(&shi[idx]);
                *(uint4*)(htlo32 + row * HT_STRIDE32 + col) = __ldcg(&slo[idx]);
            }
        }
        __syncthreads();

        // ---- mma: warp owns 16 gate rows x full k=512 ----
        float acc_a[4] = {0.f, 0.f, 0.f, 0.f};
        float acc_b[4] = {0.f, 0.f, 0.f, 0.f};
        {
            const unsigned* bh = hthi32 + gID * HT_STRIDE32;
            const unsigned* bl = htlo32 + gID * HT_STRIDE32;
            const uint4* wl = wlo_s + wid * 1024 + lane;
            #pragma unroll
            for (int kc = 0; kc < 32; kc++) {
                unsigned bh0 = bh[kc * 8 + t4];
                unsigned bh1 = bh[kc * 8 + t4 + 4];
                unsigned bl0 = bl[kc * 8 + t4];
                unsigned bl1 = bl[kc * 8 + t4 + 4];
                uint4 alo = wl[kc * 32];
                mma_bf(acc_a, ahi[kc], bh0, bh1);   // Whi * h_hi
                mma_bf(acc_b, ahi[kc], bl0, bl1);   // Whi * h_lo
                mma_bf(acc_a, alo,     bh0, bh1);   // Wlo * h_hi
            }
        }
        {
            int r = wid * 16 + gID;
            int t2 = t4 * 2;
            pg[r * PG_LD + t2]           = acc_a[0] + acc_b[0];
            pg[r * PG_LD + t2 + 1]       = acc_a[1] + acc_b[1];
            pg[(r + 8) * PG_LD + t2]     = acc_a[2] + acc_b[2];
            pg[(r + 8) * PG_LD + t2 + 1] = acc_a[3] + acc_b[3];
        }
        __syncthreads();

        // ---- finalize: 256 threads, thread = (batch=wid, h=lane) ----
        {
            float pre0 = pg[(0 * 32 + fhh) * PG_LD + fb] + xp[0];
            float pre1 = pg[(1 * 32 + fhh) * PG_LD + fb] + xp[1];
            float pre2 = pg[(2 * 32 + fhh) * PG_LD + fb] + xp[2];
            float pre3 = pg[(3 * 32 + fhh) * PG_LD + fb] + xp[3];
            float ig = fsigmoid(pre0);
            float fg = fsigmoid(pre1);
            float gt = ftanh(pre2);
            float og = fsigmoid(pre3);
            c_state = fg * c_state + ig * gt;
            float hnew = og * ftanh(c_state);

            out[(((size_t)fb * NT + t) * (2 * HDIM) + dir * HDIM + h0 + fhh) * KH + k] = hnew;

            // pair-pack via shfl: even lane packs (even, odd) and stores
            float partner = __shfl_xor_sync(0xffffffffu, hnew, 1);
            if ((fhh & 1) == 0) {
                unsigned lo;
                unsigned hi = bfsplit2(hnew, partner, lo);
                size_t off = (size_t)((par ^ 1) * NHEAD + hd) * (BSZ * 256)
                           + fb * 256 + (h0 >> 1) + (fhh >> 1);
                g_hhi[off] = hi;
                g_hlo[off] = lo;
            }
        }

        if (s < NT - 1) {
            // prefetch xproj for next step (overlaps barrier)
            int tn = dir ? (NT - 2 - s) : (s + 1);
            {
                const float* xb = &g_xproj[(((size_t)hd * NT + tn) * BSZ + fb) * GDIM + h0 + fhh];
                #pragma unroll
                for (int g = 0; g < 4; g++) xp[g] = __ldg(xb + g * HDIM);
            }
            __syncthreads();
            if (tid == 0) {
                __threadfence();   // cumulative: orders all threads' pre-sync stores at gpu scope
                *(volatile unsigned*)&g_flag[hd * CPH + ci] = (unsigned)(s + 1);
            }
            if (tid < CPH) {
                while (flg[tid] <= (unsigned)s) { }
            }
            __syncthreads();
        }
    }
}

// ---------------- launch ----------------
extern "C" void kernel_launch(void* const* d_in, const int* in_sizes, int n_in,
                              void* d_out, int out_size) {
    const float* x     = (const float*)d_in[0];
    const float* Wih_f = (const float*)d_in[1];
    const float* Whh_f = (const float*)d_in[2];
    const float* bih_f = (const float*)d_in[3];
    const float* bhh_f = (const float*)d_in[4];
    const float* Wih_b = (const float*)d_in[5];
    const float* Whh_b = (const float*)d_in[6];
    const float* bih_b = (const float*)d_in[7];
    const float* bhh_b = (const float*)d_in[8];
    float* out = (float*)d_out;

    static int smem_set = 0;
    if (!smem_set) {
        cudaFuncSetAttribute(k_lstm, cudaFuncAttributeMaxDynamicSharedMemorySize, LSTM_SMEM);
        smem_set = 1;
    }

    k_init<<<256, 256>>>();
    dim3 gx(CH / 128, NT, BSZ);
    k_xT<<<gx, 128>>>(x);
    k_wfrag<<<4096, 256>>>(Whh_f, Whh_b);
    dim3 gg(GDIM / 128, (NT * BSZ) / 128, NHEAD);
    k_gemm<<<gg, 256>>>(Wih_f, Wih_b, bih_f, bhh_f, bih_b, bhh_b);
    k_lstm<<<NCTA, 256, LSTM_SMEM>>>(out);
}